// round 1
// baseline (speedup 1.0000x reference)
#include <cuda_runtime.h>
#include <cuda_bf16.h>

// CompositeLoss: focal + sparsity + concentration over pred/target [16,20,256,256] f32.
// Single fused pass using moment expansion of the concentration term.

#define BATCH   16
#define CHANS   20
#define PLANES  (BATCH * CHANS)          // 320
#define HDIM    256
#define WDIM    256
#define HW      (HDIM * WDIM)            // 65536
#define NTOT    ((long long)PLANES * HW) // 20,971,520
#define SEGS    4                        // blocks per plane
#define THREADS 256
#define F4_PER_SEG (HW / 4 / SEGS)       // 4096 float4 per block
#define F4_PER_THREAD (F4_PER_SEG / THREADS) // 16

// Per-plane moment accumulators: [mass, s_ty, s_tx, s_p, s_py, s_px, s_pyy, s_pxx]
__device__ float  g_plane[PLANES * 8];
// Global sums: [focal_raw (a*u^2*log, negated at end), sq_sum, abs_sum]
__device__ double g_glob[3];

__global__ void zero_kernel() {
    int i = blockIdx.x * blockDim.x + threadIdx.x;
    if (i < PLANES * 8) g_plane[i] = 0.0f;
    if (i < 3) g_glob[i] = 0.0;
}

__global__ __launch_bounds__(THREADS) void main_kernel(
    const float4* __restrict__ pred, const float4* __restrict__ tgt)
{
    const int blk   = blockIdx.x;
    const int plane = blk / SEGS;
    const int seg   = blk % SEGS;
    const int base  = plane * (HW / 4) + seg * F4_PER_SEG;

    // thread-local accumulators
    float fl = 0.f, sq = 0.f, ab = 0.f;           // global terms
    float tm = 0.f, sty = 0.f, stx = 0.f;         // target moments
    float sp = 0.f, spy = 0.f, spx = 0.f;         // p moments
    float spyy = 0.f, spxx = 0.f;

    #pragma unroll
    for (int i = 0; i < F4_PER_THREAD; i++) {
        const int v  = threadIdx.x + (i << 8);          // float4 idx within segment
        const int lv = (seg * F4_PER_SEG) + v;          // float4 idx within plane
        const float4 pr = pred[base + v];
        const float4 tg = tgt[base + v];
        const float y  = (float)(lv >> 6);              // W/4 = 64 float4 per row
        const float x0 = (float)((lv & 63) << 2);

        float psum = 0.f, tsum = 0.f, pxs = 0.f, pxxs = 0.f, txs = 0.f;

        const float pv[4] = {pr.x, pr.y, pr.z, pr.w};
        const float tv[4] = {tg.x, tg.y, tg.z, tg.w};
        #pragma unroll
        for (int j = 0; j < 4; j++) {
            const float xp = pv[j];
            const float t  = tv[j];                     // 0.0 or 1.0
            const float xc = x0 + (float)j;

            // p = sigmoid(xp); 1-p = e*r
            const float e   = __expf(-xp);
            const float r   = __fdividef(1.0f, 1.0f + e);   // p
            const float omp = e * r;                         // 1-p
            const float pt  = fmaf(t, r - omp, omp);         // t ? p : 1-p
            const float a   = fmaf(-0.5f, t, 0.75f);         // t ? 0.25 : 0.75
            const float u   = 1.0f - pt;
            const float lg  = __logf(pt + 1e-8f);
            fl = fmaf(a * u * u, lg, fl);                    // (negative); negate later

            const float d = xp - t;
            sq = fmaf(d, d, sq);
            ab += fabsf(xp);

            psum += r;
            tsum += t;
            pxs  = fmaf(r, xc, pxs);
            pxxs = fmaf(r, xc * xc, pxxs);
            txs  = fmaf(t, xc, txs);
        }
        // fold row (y) moments once per float4
        sp   += psum;
        spy  = fmaf(psum, y, spy);
        spyy = fmaf(psum, y * y, spyy);
        spx  += pxs;
        spxx += pxxs;
        tm   += tsum;
        sty  = fmaf(tsum, y, sty);
        stx  += txs;
    }

    // --- block reduction of 11 values ---
    float vals[11] = {fl, sq, ab, tm, sty, stx, sp, spy, spx, spyy, spxx};
    #pragma unroll
    for (int off = 16; off > 0; off >>= 1) {
        #pragma unroll
        for (int k = 0; k < 11; k++)
            vals[k] += __shfl_down_sync(0xffffffffu, vals[k], off);
    }
    __shared__ float smem[THREADS / 32][11];
    const int w = threadIdx.x >> 5, l = threadIdx.x & 31;
    if (l == 0) {
        #pragma unroll
        for (int k = 0; k < 11; k++) smem[w][k] = vals[k];
    }
    __syncthreads();
    if (threadIdx.x == 0) {
        float r[11];
        #pragma unroll
        for (int k = 0; k < 11; k++) r[k] = smem[0][k];
        for (int ww = 1; ww < THREADS / 32; ww++)
            #pragma unroll
            for (int k = 0; k < 11; k++) r[k] += smem[ww][k];

        atomicAdd(&g_glob[0], (double)r[0]);
        atomicAdd(&g_glob[1], (double)r[1]);
        atomicAdd(&g_glob[2], (double)r[2]);
        float* P = &g_plane[plane * 8];
        #pragma unroll
        for (int k = 0; k < 8; k++) atomicAdd(&P[k], r[3 + k]);
    }
}

__global__ void finalize_kernel(float* __restrict__ out, int out_size) {
    __shared__ float s_conc;
    __shared__ int   s_nvalid;
    if (threadIdx.x == 0) { s_conc = 0.0f; s_nvalid = 0; }
    __syncthreads();

    const int i = threadIdx.x;
    if (i < PLANES) {
        const float* P = &g_plane[i * 8];
        const float mass = P[0];
        if (mass > 0.0f) {
            const float sty_ = P[1], stx_ = P[2];
            const float sp_  = P[3], spy_ = P[4], spx_ = P[5];
            const float spyy_ = P[6], spxx_ = P[7];
            const float cy = sty_ / mass;
            const float cx = stx_ / mass;
            const float num = spyy_ - 2.0f * cy * spy_ + cy * cy * sp_
                            + spxx_ - 2.0f * cx * spx_ + cx * cx * sp_;
            atomicAdd(&s_conc, num / (float)HW);
            atomicAdd(&s_nvalid, 1);
        }
    }
    __syncthreads();

    if (threadIdx.x == 0) {
        const double N = (double)NTOT;
        const float focal    = (float)(-g_glob[0] / N);
        const float sparsity = (float)(g_glob[1] / N + 1.0 * g_glob[2] / N);
        float conc = 0.0f;
        if (s_nvalid > 0) conc = s_conc / (float)s_nvalid;   // CONC_INNER_W = 1.0
        const float total = 1.0f * focal + 0.8f * sparsity + 1.5f * conc;
        out[0] = total;
        if (out_size >= 4) { out[1] = focal; out[2] = sparsity; out[3] = conc; }
    }
}

extern "C" void kernel_launch(void* const* d_in, const int* in_sizes, int n_in,
                              void* d_out, int out_size) {
    const float4* pred = (const float4*)d_in[0];
    const float4* tgt  = (const float4*)d_in[1];
    float* out = (float*)d_out;

    zero_kernel<<<(PLANES * 8 + 255) / 256, 256>>>();
    main_kernel<<<PLANES * SEGS, THREADS>>>(pred, tgt);
    finalize_kernel<<<1, 512>>>(out, out_size);
}